// round 3
// baseline (speedup 1.0000x reference)
#include <cuda_runtime.h>
#include <cstdint>
#include <cstddef>

#define N      16384
#define C      128
#define KNN    9
#define KCAND  16
#define COUT   256
#define STRIP  2048
#define NSTRIP (N / STRIP)

// Scratch (static __device__ arrays per harness rules; no cudaMalloc anywhere)
__device__ float g_sq[N];
__device__ float g_dist[(size_t)STRIP * N];   // 128 MB strip of the distance matrix
__device__ int   g_cand[N * KCAND];
__device__ int   g_nbr[N * KNN];
__device__ float g_x2[(size_t)N * C];

// ---------------------------------------------------------------------------
// 1) squared norms -- replicate an LLVM/XLA vectorized reduce:
//    VF=4, IC=2 -> 8 stride-8 fmaf partial sums, lane-wise combine of the two
//    interleaved vectors, then horizontal tree (l0+l2)+(l1+l3).
// ---------------------------------------------------------------------------
__global__ void sqnorm_kernel(const float* __restrict__ x) {
    int i = blockIdx.x * blockDim.x + threadIdx.x;
    if (i >= N) return;
    const float* r = x + (size_t)i * C;
    float p[8];
#pragma unroll
    for (int l = 0; l < 8; l++) p[l] = 0.f;
#pragma unroll
    for (int k = 0; k < C / 8; k++)
#pragma unroll
        for (int l = 0; l < 8; l++) {
            float v = r[8 * k + l];
            p[l] = fmaf(v, v, p[l]);
        }
    float v0 = p[0] + p[4];
    float v1 = p[1] + p[5];
    float v2 = p[2] + p[6];
    float v3 = p[3] + p[7];
    g_sq[i] = (v0 + v2) + (v1 + v3);
}

// ---------------------------------------------------------------------------
// 2) distance GEMM strip (candidate nomination): ascending-k fp32 FMA chains.
//    dist[i - row0][j] = sq[i] + sq[j] - 2 * x_i . x_j
// ---------------------------------------------------------------------------
__global__ __launch_bounds__(256, 2)
void dist_kernel(const float* __restrict__ x, int row0) {
    __shared__ float As[32][132];   // [k][m] transposed
    __shared__ float Bs[32][132];   // [k][n] transposed

    const int bi  = row0 + blockIdx.y * 128;
    const int bj  = blockIdx.x * 128;
    const int tid = threadIdx.x;
    const int tm  = (tid >> 4) << 3;   // 0..120
    const int tn  = (tid & 15) << 3;   // 0..120

    float acc[8][8];
#pragma unroll
    for (int a = 0; a < 8; a++)
#pragma unroll
        for (int bq = 0; bq < 8; bq++) acc[a][bq] = 0.f;

    for (int k0 = 0; k0 < C; k0 += 32) {
#pragma unroll
        for (int v = 0; v < 4; v++) {
            int idx = tid + v * 256;       // 0..1023
            int r   = idx >> 3;            // 0..127
            int c4  = (idx & 7) << 2;      // 0,4,...,28
            float4 a = *reinterpret_cast<const float4*>(&x[(size_t)(bi + r) * C + k0 + c4]);
            As[c4 + 0][r] = a.x; As[c4 + 1][r] = a.y;
            As[c4 + 2][r] = a.z; As[c4 + 3][r] = a.w;
            float4 bb = *reinterpret_cast<const float4*>(&x[(size_t)(bj + r) * C + k0 + c4]);
            Bs[c4 + 0][r] = bb.x; Bs[c4 + 1][r] = bb.y;
            Bs[c4 + 2][r] = bb.z; Bs[c4 + 3][r] = bb.w;
        }
        __syncthreads();
#pragma unroll
        for (int k = 0; k < 32; k++) {
            float av[8], bv[8];
            *reinterpret_cast<float4*>(&av[0]) = *reinterpret_cast<const float4*>(&As[k][tm]);
            *reinterpret_cast<float4*>(&av[4]) = *reinterpret_cast<const float4*>(&As[k][tm + 4]);
            *reinterpret_cast<float4*>(&bv[0]) = *reinterpret_cast<const float4*>(&Bs[k][tn]);
            *reinterpret_cast<float4*>(&bv[4]) = *reinterpret_cast<const float4*>(&Bs[k][tn + 4]);
#pragma unroll
            for (int a = 0; a < 8; a++)
#pragma unroll
                for (int bq = 0; bq < 8; bq++)
                    acc[a][bq] = fmaf(av[a], bv[bq], acc[a][bq]);
        }
        __syncthreads();
    }

    const float INFV = __int_as_float(0x7f800000);
#pragma unroll
    for (int a = 0; a < 8; a++) {
        int i      = bi + tm + a;
        int lrow   = i - row0;
        float sqi  = g_sq[i];
        float rowv[8];
#pragma unroll
        for (int bq = 0; bq < 8; bq++) {
            int j = bj + tn + bq;
            float dv = (sqi + g_sq[j]) - 2.f * acc[a][bq];
            if (i == j) dv = INFV;
            rowv[bq] = dv;
        }
        float* dst = &g_dist[(size_t)lrow * N + bj + tn];
        *reinterpret_cast<float4*>(dst)     = *reinterpret_cast<float4*>(&rowv[0]);
        *reinterpret_cast<float4*>(dst + 4) = *reinterpret_cast<float4*>(&rowv[4]);
    }
}

// ---------------------------------------------------------------------------
// 3) per-row top-16 smallest CANDIDATES (ties -> lower index)
// ---------------------------------------------------------------------------
__global__ void topk_kernel(int row0) {
    const int lrow = blockIdx.x;
    const int row  = row0 + lrow;
    const float* d = g_dist + (size_t)lrow * N;
    const int tid  = threadIdx.x;
    const float INFV = __int_as_float(0x7f800000);

    float v[KCAND];
    int   id[KCAND];
#pragma unroll
    for (int q = 0; q < KCAND; q++) { v[q] = INFV; id[q] = 0x7fffffff; }

    // thread-local sorted (ascending) top-16 over strided columns
    for (int j = tid; j < N; j += 256) {
        float dv = d[j];
        if (dv < v[KCAND - 1]) {
            int pos = KCAND - 1;
            while (pos > 0 && dv < v[pos - 1]) {
                v[pos] = v[pos - 1]; id[pos] = id[pos - 1]; pos--;
            }
            v[pos] = dv; id[pos] = j;
        }
    }

    __shared__ float cv[256];
    __shared__ int   ci[256];
    int p = 0;
    for (int round = 0; round < KCAND; round++) {
        cv[tid] = (p < KCAND) ? v[p]  : INFV;
        ci[tid] = (p < KCAND) ? id[p] : 0x7fffffff;
        __syncthreads();
        for (int s = 128; s > 0; s >>= 1) {
            if (tid < s) {
                float ov = cv[tid + s]; int oi = ci[tid + s];
                if (ov < cv[tid] || (ov == cv[tid] && oi < ci[tid])) {
                    cv[tid] = ov; ci[tid] = oi;
                }
            }
            __syncthreads();
        }
        int win = ci[0];
        __syncthreads();   // everyone has read ci[0] before next round overwrites
        if (tid == 0) g_cand[row * KCAND + round] = win;
        if (p < KCAND && id[p] == win) p++;
    }
}

// ---------------------------------------------------------------------------
// 3b) authoritative fp32 re-rank of the 16 candidates, replicating the
//     reference arithmetic: dot = single ascending-k fp32 FMA chain,
//     d = (sq_i + sq_j) - 2*dot, tie-break by lower index.
//     One warp per row; lane t owns candidate t.
// ---------------------------------------------------------------------------
__global__ __launch_bounds__(128)
void refine_kernel(const float* __restrict__ x) {
    __shared__ float sxi[4][128];
    const int warp = threadIdx.x >> 5;
    const int lane = threadIdx.x & 31;
    const int row  = blockIdx.x * 4 + warp;

#pragma unroll
    for (int q = 0; q < 4; q++)
        sxi[warp][lane + 32 * q] = x[(size_t)row * C + lane + 32 * q];
    __syncwarp();

    float d = __int_as_float(0x7f800000);
    int   j = 0x7fffffff;
    if (lane < KCAND) {
        j = g_cand[row * KCAND + lane];
        const float* xj = x + (size_t)j * C;
        float acc = 0.f;
#pragma unroll
        for (int k = 0; k < C; k += 4) {
            float4 v = *reinterpret_cast<const float4*>(xj + k);
            acc = fmaf(sxi[warp][k + 0], v.x, acc);
            acc = fmaf(sxi[warp][k + 1], v.y, acc);
            acc = fmaf(sxi[warp][k + 2], v.z, acc);
            acc = fmaf(sxi[warp][k + 3], v.w, acc);
        }
        d = (g_sq[row] + g_sq[j]) - 2.f * acc;
    }

    // lane 0 gathers, sorts by (d, index), writes the 9 nearest
    float dv[KCAND];
    int   di[KCAND];
#pragma unroll
    for (int t = 0; t < KCAND; t++) {
        dv[t] = __shfl_sync(0xffffffffu, d, t);
        di[t] = __shfl_sync(0xffffffffu, j, t);
    }
    if (lane == 0) {
#pragma unroll
        for (int a = 1; a < KCAND; a++) {
            float cvv = dv[a]; int cii = di[a];
            int p = a - 1;
            while (p >= 0 && (dv[p] > cvv || (dv[p] == cvv && di[p] > cii))) {
                dv[p + 1] = dv[p]; di[p + 1] = di[p]; p--;
            }
            dv[p + 1] = cvv; di[p + 1] = cii;
        }
#pragma unroll
        for (int t = 0; t < KNN; t++) g_nbr[row * KNN + t] = di[t];
    }
}

// ---------------------------------------------------------------------------
// 4) x2 = x + rel_pos_table[rel], rel[i] = i/128 - i%128 + 127
// ---------------------------------------------------------------------------
__global__ void relpos_kernel(const float* __restrict__ x, const float* __restrict__ tab) {
    int idx = blockIdx.x * blockDim.x + threadIdx.x;   // over N*C
    int i   = idx >> 7;
    int c   = idx & 127;
    int rel = (i >> 7) - (i & 127) + (C - 1);
    g_x2[idx] = x[idx] + tab[(size_t)rel * C + c];
}

// ---------------------------------------------------------------------------
// 5) gather + max-relative + concat-GEMM (+ bias at the end). 16 rows/block.
//    Accumulation: ascending-f single fp32 FMA chain, bias added LAST
//    (matches reference: matmul then +b).
// ---------------------------------------------------------------------------
__global__ __launch_bounds__(256)
void final_kernel(const float* __restrict__ W, const float* __restrict__ b,
                  float* __restrict__ out) {
    __shared__ float feat[16][260];   // [x2 | m], padded row
    const int r0   = blockIdx.x * 16;
    const int tid  = threadIdx.x;
    const int half = tid >> 7;
    const int c    = tid & 127;
    const float NEGINF = __int_as_float(0xff800000);

#pragma unroll
    for (int rr = 0; rr < 16; rr += 2) {
        int r = rr + half;
        int i = r0 + r;
        float xi = g_x2[(size_t)i * C + c];
        float m  = NEGINF;
#pragma unroll
        for (int k = 0; k < KNN; k++) {
            int j = g_nbr[i * KNN + k];
            m = fmaxf(m, g_x2[(size_t)j * C + c] - xi);
        }
        feat[r][c]     = xi;
        feat[r][C + c] = m;
    }
    __syncthreads();

    const int o = tid;   // output column 0..255
    float acc[16];
#pragma unroll
    for (int r = 0; r < 16; r++) acc[r] = 0.f;

    for (int f = 0; f < 2 * C; f += 4) {
        float w0 = W[(size_t)(f + 0) * COUT + o];
        float w1 = W[(size_t)(f + 1) * COUT + o];
        float w2 = W[(size_t)(f + 2) * COUT + o];
        float w3 = W[(size_t)(f + 3) * COUT + o];
#pragma unroll
        for (int r = 0; r < 16; r++) {
            float4 fv = *reinterpret_cast<const float4*>(&feat[r][f]);
            acc[r] = fmaf(fv.x, w0, acc[r]);
            acc[r] = fmaf(fv.y, w1, acc[r]);
            acc[r] = fmaf(fv.z, w2, acc[r]);
            acc[r] = fmaf(fv.w, w3, acc[r]);
        }
    }
    float bias = b[o];
#pragma unroll
    for (int r = 0; r < 16; r++)
        out[(size_t)(r0 + r) * COUT + o] = acc[r] + bias;
}

// ---------------------------------------------------------------------------
extern "C" void kernel_launch(void* const* d_in, const int* in_sizes, int n_in,
                              void* d_out, int out_size) {
    const float* x   = (const float*)d_in[0];
    const float* tab = (const float*)d_in[1];
    const float* W   = (const float*)d_in[2];
    const float* b   = (const float*)d_in[3];
    float* out = (float*)d_out;
    (void)in_sizes; (void)n_in; (void)out_size;

    sqnorm_kernel<<<(N + 255) / 256, 256>>>(x);
    for (int s = 0; s < NSTRIP; s++) {
        dist_kernel<<<dim3(N / 128, STRIP / 128), 256>>>(x, s * STRIP);
        topk_kernel<<<STRIP, 256>>>(s * STRIP);
    }
    refine_kernel<<<N / 4, 128>>>(x);
    relpos_kernel<<<(N * C) / 256, 256>>>(x, tab);
    final_kernel<<<N / 16, 256>>>(W, b, out);
}

// round 4
// speedup vs baseline: 3.0968x; 3.0968x over previous
#include <cuda_runtime.h>
#include <cstdint>
#include <cstddef>

#define N      16384
#define C      128
#define KNN    9
#define KCAND  16
#define COUT   256
#define STRIP  2048
#define NSTRIP (N / STRIP)

// Scratch (static __device__ arrays per harness rules; no cudaMalloc anywhere)
__device__ float g_sq[N];
__device__ float g_dist[(size_t)STRIP * N];   // 128 MB strip of the distance matrix
__device__ int   g_cand[N * KCAND];
__device__ int   g_nbr[N * KNN];
__device__ float g_x2[(size_t)N * C];

// ---------------------------------------------------------------------------
// 1) squared norms -- replicate an LLVM/XLA vectorized reduce:
//    VF=4, IC=2 -> 8 stride-8 fmaf partial sums, lane-wise combine of the two
//    interleaved vectors, then horizontal tree (l0+l2)+(l1+l3).
// ---------------------------------------------------------------------------
__global__ void sqnorm_kernel(const float* __restrict__ x) {
    int i = blockIdx.x * blockDim.x + threadIdx.x;
    if (i >= N) return;
    const float* r = x + (size_t)i * C;
    float p[8];
#pragma unroll
    for (int l = 0; l < 8; l++) p[l] = 0.f;
#pragma unroll
    for (int k = 0; k < C / 8; k++)
#pragma unroll
        for (int l = 0; l < 8; l++) {
            float v = r[8 * k + l];
            p[l] = fmaf(v, v, p[l]);
        }
    float v0 = p[0] + p[4];
    float v1 = p[1] + p[5];
    float v2 = p[2] + p[6];
    float v3 = p[3] + p[7];
    g_sq[i] = (v0 + v2) + (v1 + v3);
}

// ---------------------------------------------------------------------------
// 2) distance GEMM strip (candidate nomination): ascending-k fp32 FMA chains.
//    dist[i - row0][j] = sq[i] + sq[j] - 2 * x_i . x_j
// ---------------------------------------------------------------------------
__global__ __launch_bounds__(256, 2)
void dist_kernel(const float* __restrict__ x, int row0) {
    __shared__ float As[32][132];   // [k][m] transposed
    __shared__ float Bs[32][132];   // [k][n] transposed

    const int bi  = row0 + blockIdx.y * 128;
    const int bj  = blockIdx.x * 128;
    const int tid = threadIdx.x;
    const int tm  = (tid >> 4) << 3;   // 0..120
    const int tn  = (tid & 15) << 3;   // 0..120

    float acc[8][8];
#pragma unroll
    for (int a = 0; a < 8; a++)
#pragma unroll
        for (int bq = 0; bq < 8; bq++) acc[a][bq] = 0.f;

    for (int k0 = 0; k0 < C; k0 += 32) {
#pragma unroll
        for (int v = 0; v < 4; v++) {
            int idx = tid + v * 256;       // 0..1023
            int r   = idx >> 3;            // 0..127
            int c4  = (idx & 7) << 2;      // 0,4,...,28
            float4 a = *reinterpret_cast<const float4*>(&x[(size_t)(bi + r) * C + k0 + c4]);
            As[c4 + 0][r] = a.x; As[c4 + 1][r] = a.y;
            As[c4 + 2][r] = a.z; As[c4 + 3][r] = a.w;
            float4 bb = *reinterpret_cast<const float4*>(&x[(size_t)(bj + r) * C + k0 + c4]);
            Bs[c4 + 0][r] = bb.x; Bs[c4 + 1][r] = bb.y;
            Bs[c4 + 2][r] = bb.z; Bs[c4 + 3][r] = bb.w;
        }
        __syncthreads();
#pragma unroll
        for (int k = 0; k < 32; k++) {
            float av[8], bv[8];
            *reinterpret_cast<float4*>(&av[0]) = *reinterpret_cast<const float4*>(&As[k][tm]);
            *reinterpret_cast<float4*>(&av[4]) = *reinterpret_cast<const float4*>(&As[k][tm + 4]);
            *reinterpret_cast<float4*>(&bv[0]) = *reinterpret_cast<const float4*>(&Bs[k][tn]);
            *reinterpret_cast<float4*>(&bv[4]) = *reinterpret_cast<const float4*>(&Bs[k][tn + 4]);
#pragma unroll
            for (int a = 0; a < 8; a++)
#pragma unroll
                for (int bq = 0; bq < 8; bq++)
                    acc[a][bq] = fmaf(av[a], bv[bq], acc[a][bq]);
        }
        __syncthreads();
    }

    const float INFV = __int_as_float(0x7f800000);
#pragma unroll
    for (int a = 0; a < 8; a++) {
        int i      = bi + tm + a;
        int lrow   = i - row0;
        float sqi  = g_sq[i];
        float rowv[8];
#pragma unroll
        for (int bq = 0; bq < 8; bq++) {
            int j = bj + tn + bq;
            float dv = (sqi + g_sq[j]) - 2.f * acc[a][bq];
            if (i == j) dv = INFV;
            rowv[bq] = dv;
        }
        float* dst = &g_dist[(size_t)lrow * N + bj + tn];
        *reinterpret_cast<float4*>(dst)     = *reinterpret_cast<float4*>(&rowv[0]);
        *reinterpret_cast<float4*>(dst + 4) = *reinterpret_cast<float4*>(&rowv[4]);
    }
}

// ---------------------------------------------------------------------------
// 3) per-row top-16 smallest CANDIDATES (ties -> lower index).
//    Register-resident unrolled insertion (NO local memory), shared-memory
//    tournament for the block merge.
// ---------------------------------------------------------------------------
__global__ __launch_bounds__(256)
void topk_kernel(int row0) {
    __shared__ float sv[256][KCAND + 1];
    __shared__ int   si[256][KCAND + 1];
    __shared__ float wv[8];
    __shared__ int   wi[8];
    __shared__ int   s_win;

    const int lrow = blockIdx.x;
    const int row  = row0 + lrow;
    const float* d = g_dist + (size_t)lrow * N;
    const int tid  = threadIdx.x;
    const int lane = tid & 31;
    const int warp = tid >> 5;
    const float INFV = __int_as_float(0x7f800000);

    float v[KCAND];
    int   id[KCAND];
#pragma unroll
    for (int q = 0; q < KCAND; q++) { v[q] = INFV; id[q] = 0x7fffffff; }
    float worst = INFV;

    const float4* d4 = reinterpret_cast<const float4*>(d);
#pragma unroll 4
    for (int it = 0; it < N / (256 * 4); it++) {
        float4 q4 = d4[it * 256 + tid];
        int jb = (it * 256 + tid) * 4;
        float cand[4] = {q4.x, q4.y, q4.z, q4.w};
#pragma unroll
        for (int e = 0; e < 4; e++) {
            float dv = cand[e];
            if (dv < worst) {          // rare after warmup; guard is a register cmp
                int jj = jb + e;
#pragma unroll
                for (int q = 0; q < KCAND; q++) {   // unrolled compare-swap chain
                    bool sw = dv < v[q];
                    float tv = sw ? v[q] : dv;  v[q]  = sw ? dv : v[q];  dv = tv;
                    int   ti = sw ? id[q] : jj; id[q] = sw ? jj : id[q]; jj = ti;
                }
                worst = v[KCAND - 1];
            }
        }
    }

    // dump sorted per-thread lists to shared
#pragma unroll
    for (int q = 0; q < KCAND; q++) { sv[tid][q] = v[q]; si[tid][q] = id[q]; }
    __syncthreads();

    int p = 0;   // head pointer into this thread's shared list
    for (int round = 0; round < KCAND; round++) {
        float mv = (p < KCAND) ? sv[tid][p] : INFV;
        int   mi = (p < KCAND) ? si[tid][p] : 0x7fffffff;
#pragma unroll
        for (int s = 16; s > 0; s >>= 1) {
            float ov = __shfl_xor_sync(0xffffffffu, mv, s);
            int   oi = __shfl_xor_sync(0xffffffffu, mi, s);
            if (ov < mv || (ov == mv && oi < mi)) { mv = ov; mi = oi; }
        }
        if (lane == 0) { wv[warp] = mv; wi[warp] = mi; }
        __syncthreads();
        if (tid == 0) {
            float bv = wv[0]; int bi = wi[0];
#pragma unroll
            for (int w = 1; w < 8; w++)
                if (wv[w] < bv || (wv[w] == bv && wi[w] < bi)) { bv = wv[w]; bi = wi[w]; }
            s_win = bi;
            g_cand[row * KCAND + round] = bi;
        }
        __syncthreads();
        if (p < KCAND && si[tid][p] == s_win) p++;   // column sets disjoint -> unique
    }
}

// ---------------------------------------------------------------------------
// 3b) authoritative fp32 re-rank of the 16 candidates, replicating the
//     reference arithmetic: dot = single ascending-k fp32 FMA chain,
//     d = (sq_i + sq_j) - 2*dot, tie-break by lower index.
//     One warp per row; lane t owns candidate t.
// ---------------------------------------------------------------------------
__global__ __launch_bounds__(128)
void refine_kernel(const float* __restrict__ x) {
    __shared__ float sxi[4][128];
    const int warp = threadIdx.x >> 5;
    const int lane = threadIdx.x & 31;
    const int row  = blockIdx.x * 4 + warp;

#pragma unroll
    for (int q = 0; q < 4; q++)
        sxi[warp][lane + 32 * q] = x[(size_t)row * C + lane + 32 * q];
    __syncwarp();

    float d = __int_as_float(0x7f800000);
    int   j = 0x7fffffff;
    if (lane < KCAND) {
        j = g_cand[row * KCAND + lane];
        const float* xj = x + (size_t)j * C;
        float acc = 0.f;
#pragma unroll
        for (int k = 0; k < C; k += 4) {
            float4 v = *reinterpret_cast<const float4*>(xj + k);
            acc = fmaf(sxi[warp][k + 0], v.x, acc);
            acc = fmaf(sxi[warp][k + 1], v.y, acc);
            acc = fmaf(sxi[warp][k + 2], v.z, acc);
            acc = fmaf(sxi[warp][k + 3], v.w, acc);
        }
        d = (g_sq[row] + g_sq[j]) - 2.f * acc;
    }

    // lane 0 gathers, sorts by (d, index) with a static bubble network
    float dv[KCAND];
    int   di[KCAND];
#pragma unroll
    for (int t = 0; t < KCAND; t++) {
        dv[t] = __shfl_sync(0xffffffffu, d, t);
        di[t] = __shfl_sync(0xffffffffu, j, t);
    }
    if (lane == 0) {
#pragma unroll
        for (int a = 0; a < KCAND - 1; a++)
#pragma unroll
            for (int bq = 0; bq < KCAND - 1; bq++) {
                bool sw = dv[bq] > dv[bq + 1] ||
                          (dv[bq] == dv[bq + 1] && di[bq] > di[bq + 1]);
                float tv = sw ? dv[bq + 1] : dv[bq];
                dv[bq + 1] = sw ? dv[bq] : dv[bq + 1]; dv[bq] = tv;
                int ti = sw ? di[bq + 1] : di[bq];
                di[bq + 1] = sw ? di[bq] : di[bq + 1]; di[bq] = ti;
            }
#pragma unroll
        for (int t = 0; t < KNN; t++) g_nbr[row * KNN + t] = di[t];
    }
}

// ---------------------------------------------------------------------------
// 4) x2 = x + rel_pos_table[rel], rel[i] = i/128 - i%128 + 127
// ---------------------------------------------------------------------------
__global__ void relpos_kernel(const float* __restrict__ x, const float* __restrict__ tab) {
    int idx = blockIdx.x * blockDim.x + threadIdx.x;   // over N*C
    int i   = idx >> 7;
    int c   = idx & 127;
    int rel = (i >> 7) - (i & 127) + (C - 1);
    g_x2[idx] = x[idx] + tab[(size_t)rel * C + c];
}

// ---------------------------------------------------------------------------
// 5) gather + max-relative + concat-GEMM (+ bias at the end). 16 rows/block.
// ---------------------------------------------------------------------------
__global__ __launch_bounds__(256)
void final_kernel(const float* __restrict__ W, const float* __restrict__ b,
                  float* __restrict__ out) {
    __shared__ float feat[16][260];   // [x2 | m], padded row
    const int r0   = blockIdx.x * 16;
    const int tid  = threadIdx.x;
    const int half = tid >> 7;
    const int c    = tid & 127;
    const float NEGINF = __int_as_float(0xff800000);

#pragma unroll
    for (int rr = 0; rr < 16; rr += 2) {
        int r = rr + half;
        int i = r0 + r;
        float xi = g_x2[(size_t)i * C + c];
        float m  = NEGINF;
#pragma unroll
        for (int k = 0; k < KNN; k++) {
            int j = g_nbr[i * KNN + k];
            m = fmaxf(m, g_x2[(size_t)j * C + c] - xi);
        }
        feat[r][c]     = xi;
        feat[r][C + c] = m;
    }
    __syncthreads();

    const int o = tid;   // output column 0..255
    float acc[16];
#pragma unroll
    for (int r = 0; r < 16; r++) acc[r] = 0.f;

    for (int f = 0; f < 2 * C; f += 4) {
        float w0 = W[(size_t)(f + 0) * COUT + o];
        float w1 = W[(size_t)(f + 1) * COUT + o];
        float w2 = W[(size_t)(f + 2) * COUT + o];
        float w3 = W[(size_t)(f + 3) * COUT + o];
#pragma unroll
        for (int r = 0; r < 16; r++) {
            float4 fv = *reinterpret_cast<const float4*>(&feat[r][f]);
            acc[r] = fmaf(fv.x, w0, acc[r]);
            acc[r] = fmaf(fv.y, w1, acc[r]);
            acc[r] = fmaf(fv.z, w2, acc[r]);
            acc[r] = fmaf(fv.w, w3, acc[r]);
        }
    }
    float bias = b[o];
#pragma unroll
    for (int r = 0; r < 16; r++)
        out[(size_t)(r0 + r) * COUT + o] = acc[r] + bias;
}

// ---------------------------------------------------------------------------
extern "C" void kernel_launch(void* const* d_in, const int* in_sizes, int n_in,
                              void* d_out, int out_size) {
    const float* x   = (const float*)d_in[0];
    const float* tab = (const float*)d_in[1];
    const float* W   = (const float*)d_in[2];
    const float* b   = (const float*)d_in[3];
    float* out = (float*)d_out;
    (void)in_sizes; (void)n_in; (void)out_size;

    sqnorm_kernel<<<(N + 255) / 256, 256>>>(x);
    for (int s = 0; s < NSTRIP; s++) {
        dist_kernel<<<dim3(N / 128, STRIP / 128), 256>>>(x, s * STRIP);
        topk_kernel<<<STRIP, 256>>>(s * STRIP);
    }
    refine_kernel<<<N / 4, 128>>>(x);
    relpos_kernel<<<(N * C) / 256, 256>>>(x, tab);
    final_kernel<<<N / 16, 256>>>(W, b, out);
}